// round 13
// baseline (speedup 1.0000x reference)
#include <cuda_runtime.h>
#include <math_constants.h>

// Fused: ConvTranspose3d(3->16, k=3, s=2, p=1, out_pad=1) + bias + MaxPool3d(2)
//        + softmax(ch) - subtract, swish, max(ch).
// x: [4,3,64,64,64] f32, w: [3,16,3,3,3], b: [16], subtract: [16] -> out [4,64,64,64]
//
// R13: thread-per-voxel. Each thread computes all 16 channels of one output
// voxel sequentially; weights stream from smem as pure broadcasts (all lanes
// same address -> zero conflicts, zero weight registers). Channel softmax is
// in-thread (no shuffles at all): pass1 accumulates S = sum exp(m_c) with e_c
// parked in smem (lane-consecutive), one rcp(S), pass2 does sub/swish/max.
// Natural reg demand ~75-85 -> 5-6 blocks/SM without forced launch_bounds.

#define CIN 3
#define COUT 16
#define DIM 64
#define WSTRIDE 84   // 81 taps + bias + subtract + pad, 16B-aligned rows

// tap t (0..80): cin=t/27, r=t%27, kd=r/9, kh=(r/3)%3, kw=r%3
// candidate = (kd==1?0:4)+(kh==1?0:2)+(kw==1?0:1)
// x comb    = cin*4 + (kd==0?2:0) + (kh==0?1:0) ; x offset = (kw==0)?1:0
#define TAP(t, wv_) do {                                                   \
    const int _cin = (t) / 27, _r = (t) % 27;                              \
    const int _kd = _r / 9, _kh = (_r / 3) % 3, _kw = _r % 3;              \
    const int _ci = (_kd == 1 ? 0 : 4) + (_kh == 1 ? 0 : 2)                \
                  + (_kw == 1 ? 0 : 1);                                    \
    const int _cb = _cin * 4 + (_kd == 0 ? 2 : 0) + (_kh == 0 ? 1 : 0);    \
    const int _ww = (_kw == 0) ? 1 : 0;                                    \
    acc[_ci] = fmaf((wv_), xr[_cb][_ww], acc[_ci]);                        \
} while (0)

__global__ __launch_bounds__(128) void fused_ctmp_softswish_kernel(
    const float* __restrict__ x,
    const float* __restrict__ wgt,
    const float* __restrict__ bias_g,
    const float* __restrict__ sub_g,
    float* __restrict__ out)
{
    // x tile per warp: 12 combs x 34 w-positions (one 32-voxel half + 2)
    __shared__ float xt[4][12][34];
    // weights: wsm[c*84 + t]; t=81 -> bias[c], t=82 -> subtract[c], t=83 -> 0
    __shared__ float wsm[COUT * WSTRIDE];
    // pass1 scratch: e_c per (warp, channel, lane) - same thread writes+reads
    __shared__ float esm[4][COUT][32];

    const int tid  = threadIdx.x;
    const int lane = tid & 31;
    const int wid  = tid >> 5;

    // ---- one-time: pack weights (+bias,+subtract) into smem ----
    for (int idx = tid; idx < COUT * WSTRIDE; idx += 128) {
        const int c = idx / WSTRIDE;
        const int t = idx - c * WSTRIDE;
        float v = 0.f;
        if (t < 81) {
            const int cin = t / 27, r = t % 27;
            v = __ldg(&wgt[(cin * COUT + c) * 27 + r]);
        } else if (t == 81) {
            v = __ldg(&bias_g[c]);
        } else if (t == 82) {
            v = __ldg(&sub_g[c]);
        }
        wsm[idx] = v;
    }
    __syncthreads();

    const int gwarp  = blockIdx.x * 4 + wid;
    const int nwarps = gridDim.x * 4;
    const int nunits = 4 * DIM * DIM * 2;   // (n,d,h) rows x 2 w-halves

    for (int unit = gwarp; unit < nunits; unit += nwarps) {
        const int halfu = unit & 1;
        const int row   = unit >> 1;
        const int h = row & 63;
        const int d = (row >> 6) & 63;
        const int n = row >> 12;
        const int wbase = halfu * 32;

        // ---- build x tile for this half-row ----
        #pragma unroll
        for (int comb = 0; comb < 12; ++comb) {
            const int cin = comb >> 2;
            const int dd  = (comb >> 1) & 1;
            const int hh  = comb & 1;
            const int dcur = d + dd;
            const int hcur = h + hh;
            const bool rowok = (dcur < DIM) && (hcur < DIM);
            const float* src = x + (((n * CIN + cin) * DIM + dcur) * DIM + hcur) * DIM;
            #pragma unroll
            for (int wp = lane; wp < 34; wp += 32) {
                const int wg = wbase + wp;
                float v = 0.f;
                if (rowok && wg < DIM) v = __ldg(&src[wg]);
                xt[wid][comb][wp] = v;
            }
        }
        __syncwarp();

        // ---- this thread's 24 x values into registers ----
        float xr[12][2];
        #pragma unroll
        for (int comb = 0; comb < 12; ++comb) {
            xr[comb][0] = xt[wid][comb][lane];
            xr[comb][1] = xt[wid][comb][lane + 1];
        }

        // ---- pass 1: per-channel conv + maxpool + exp, accumulate S ----
        float S = 0.f;
        #pragma unroll 2
        for (int c = 0; c < COUT; ++c) {
            const float4* wc = reinterpret_cast<const float4*>(&wsm[c * WSTRIDE]);

            float acc[8];
            #pragma unroll
            for (int i = 0; i < 8; ++i) acc[i] = 0.f;

            #pragma unroll
            for (int g = 0; g < 20; ++g) {
                const float4 w4 = wc[g];   // broadcast LDS.128
                TAP(4 * g + 0, w4.x);
                TAP(4 * g + 1, w4.y);
                TAP(4 * g + 2, w4.z);
                TAP(4 * g + 3, w4.w);
            }
            const float4 wlast = wc[20];   // {tap80, bias, subtract, 0}
            TAP(80, wlast.x);

            float m = fmaxf(fmaxf(fmaxf(acc[0], acc[1]), fmaxf(acc[2], acc[3])),
                            fmaxf(fmaxf(acc[4], acc[5]), fmaxf(acc[6], acc[7])));
            m += wlast.y;   // bias

            const float e = __expf(m);     // no max-pass: m bounded, exp safe
            S += e;
            esm[wid][c][lane] = e;         // same thread reads it back
        }

        float rS;
        asm("rcp.approx.f32 %0, %1;" : "=f"(rS) : "f"(S));

        // ---- pass 2: softmax -> subtract -> swish -> channel max ----
        float best = -CUDART_INF_F;
        #pragma unroll 4
        for (int c = 0; c < COUT; ++c) {
            const float e   = esm[wid][c][lane];
            const float sub = wsm[c * WSTRIDE + 82];   // broadcast
            const float z   = fmaf(e, rS, -sub);
            const float r   = __fdividef(z, 1.f + __expf(-z));   // swish
            best = fmaxf(best, r);
        }

        out[row * DIM + wbase + lane] = best;
        __syncwarp();   // tile reuse barrier before next unit
    }
}

extern "C" void kernel_launch(void* const* d_in, const int* in_sizes, int n_in,
                              void* d_out, int out_size) {
    const float* x   = (const float*)d_in[0];
    const float* w   = (const float*)d_in[1];
    const float* b   = (const float*)d_in[2];
    const float* sub = (const float*)d_in[3];
    float* out = (float*)d_out;
    (void)in_sizes; (void)n_in; (void)out_size;

    // exact-fit persistent grid: occupancy-determined blocks/SM x numSMs
    int dev = 0, sms = 148, bpm = 4;
    cudaGetDevice(&dev);
    cudaDeviceGetAttribute(&sms, cudaDevAttrMultiProcessorCount, dev);
    cudaOccupancyMaxActiveBlocksPerMultiprocessor(&bpm, fused_ctmp_softswish_kernel, 128, 0);
    if (bpm < 1) bpm = 1;
    fused_ctmp_softswish_kernel<<<sms * bpm, 128>>>(x, w, b, sub, out);
}

// round 14
// speedup vs baseline: 1.3486x; 1.3486x over previous
#include <cuda_runtime.h>
#include <math_constants.h>

// Fused: ConvTranspose3d(3->16, k=3, s=2, p=1, out_pad=1) + bias + MaxPool3d(2)
//        + softmax(ch) - subtract, swish, max(ch).
// x: [4,3,64,64,64] f32, w: [3,16,3,3,3], b: [16], subtract: [16] -> out [4,64,64,64]
//
// R14: thread-per-2-voxels. Warp owns a full 64-voxel row; thread owns voxels
// {2*lane, 2*lane+1} (adjacent => x windows overlap: xr[12][3]). All 16
// channels computed sequentially per thread; weights stream from smem as pure
// broadcasts, each LDS.128 now feeding 2 voxels (halves R13's L1 pressure,
// which was the 77.6% bottleneck). No shuffles anywhere; softmax in-thread
// (e parked in conflict-free smem), no max-pass (m bounded, exp safe).

#define CIN 3
#define COUT 16
#define DIM 64
#define WSTRIDE 84   // 81 taps + bias + subtract + pad

// tap t (0..80): cin=t/27, r=t%27, kd=r/9, kh=(r/3)%3, kw=r%3
// candidate = (kd==1?0:4)+(kh==1?0:2)+(kw==1?0:1)
// x comb    = cin*4 + (kd==0?2:0) + (kh==0?1:0) ; x offset = (kw==0)?1:0
// voxel vv adds +vv to the x offset.
#define TAP(t, wv_) do {                                                   \
    const int _cin = (t) / 27, _r = (t) % 27;                              \
    const int _kd = _r / 9, _kh = (_r / 3) % 3, _kw = _r % 3;              \
    const int _ci = (_kd == 1 ? 0 : 4) + (_kh == 1 ? 0 : 2)                \
                  + (_kw == 1 ? 0 : 1);                                    \
    const int _cb = _cin * 4 + (_kd == 0 ? 2 : 0) + (_kh == 0 ? 1 : 0);    \
    const int _ww = (_kw == 0) ? 1 : 0;                                    \
    acc[0][_ci] = fmaf((wv_), xr[_cb][_ww],     acc[0][_ci]);              \
    acc[1][_ci] = fmaf((wv_), xr[_cb][_ww + 1], acc[1][_ci]);              \
} while (0)

__global__ __launch_bounds__(128) void fused_ctmp_softswish_kernel(
    const float* __restrict__ x,
    const float* __restrict__ wgt,
    const float* __restrict__ bias_g,
    const float* __restrict__ sub_g,
    float* __restrict__ out)
{
    // x tile per warp: 12 combs x full row + 2 pad (indices 64,65 are zero)
    __shared__ float xt[4][12][66];
    // weights: wsm[c*84 + t]; t=81 -> bias[c], t=82 -> subtract[c], t=83 -> 0
    __shared__ float wsm[COUT * WSTRIDE];
    // pass1 scratch: e per (warp, channel, voxel-slot, lane) - conflict-free
    __shared__ float esm[4][COUT][2][32];

    const int tid  = threadIdx.x;
    const int lane = tid & 31;
    const int wid  = tid >> 5;

    // ---- one-time: pack weights (+bias,+subtract) into smem ----
    for (int idx = tid; idx < COUT * WSTRIDE; idx += 128) {
        const int c = idx / WSTRIDE;
        const int t = idx - c * WSTRIDE;
        float v = 0.f;
        if (t < 81) {
            const int cin = t / 27, r = t % 27;
            v = __ldg(&wgt[(cin * COUT + c) * 27 + r]);
        } else if (t == 81) {
            v = __ldg(&bias_g[c]);
        } else if (t == 82) {
            v = __ldg(&sub_g[c]);
        }
        wsm[idx] = v;
    }
    __syncthreads();

    const int gwarp  = blockIdx.x * 4 + wid;
    const int nwarps = gridDim.x * 4;
    const int nrows  = 4 * DIM * DIM;   // 16384 (n,d,h) rows; warp does whole row

    for (int row = gwarp; row < nrows; row += nwarps) {
        const int h = row & 63;
        const int d = (row >> 6) & 63;
        const int n = row >> 12;

        // ---- build x tile for this row ----
        #pragma unroll
        for (int comb = 0; comb < 12; ++comb) {
            const int cin = comb >> 2;
            const int dd  = (comb >> 1) & 1;
            const int hh  = comb & 1;
            const int dcur = d + dd;
            const int hcur = h + hh;
            const bool rowok = (dcur < DIM) && (hcur < DIM);
            const float* src = x + (((n * CIN + cin) * DIM + dcur) * DIM + hcur) * DIM;
            #pragma unroll
            for (int wp = lane; wp < 66; wp += 32) {
                float v = 0.f;
                if (rowok && wp < DIM) v = __ldg(&src[wp]);
                xt[wid][comb][wp] = v;
            }
        }
        __syncwarp();

        // ---- this thread's 36 x values (2 adjacent voxels, shared window) ----
        float xr[12][3];
        #pragma unroll
        for (int comb = 0; comb < 12; ++comb) {
            xr[comb][0] = xt[wid][comb][2 * lane];
            xr[comb][1] = xt[wid][comb][2 * lane + 1];
            xr[comb][2] = xt[wid][comb][2 * lane + 2];
        }

        // ---- pass 1: per-channel conv + maxpool + exp for both voxels ----
        float S0 = 0.f, S1 = 0.f;
        #pragma unroll 2
        for (int c = 0; c < COUT; ++c) {
            const float4* wc = reinterpret_cast<const float4*>(&wsm[c * WSTRIDE]);

            float acc[2][8];
            #pragma unroll
            for (int vv = 0; vv < 2; ++vv)
                #pragma unroll
                for (int i = 0; i < 8; ++i) acc[vv][i] = 0.f;

            #pragma unroll
            for (int g = 0; g < 20; ++g) {
                const float4 w4 = wc[g];   // broadcast LDS.128, feeds 2 voxels
                TAP(4 * g + 0, w4.x);
                TAP(4 * g + 1, w4.y);
                TAP(4 * g + 2, w4.z);
                TAP(4 * g + 3, w4.w);
            }
            const float4 wlast = wc[20];   // {tap80, bias, subtract, 0}
            TAP(80, wlast.x);

            #pragma unroll
            for (int vv = 0; vv < 2; ++vv) {
                const float* a = acc[vv];
                float m = fmaxf(fmaxf(fmaxf(a[0], a[1]), fmaxf(a[2], a[3])),
                                fmaxf(fmaxf(a[4], a[5]), fmaxf(a[6], a[7])));
                m += wlast.y;   // bias
                const float e = __expf(m);   // no max-pass: m bounded
                if (vv == 0) S0 += e; else S1 += e;
                esm[wid][c][vv][lane] = e;
            }
        }

        float rS0, rS1;
        asm("rcp.approx.f32 %0, %1;" : "=f"(rS0) : "f"(S0));
        asm("rcp.approx.f32 %0, %1;" : "=f"(rS1) : "f"(S1));

        // ---- pass 2: softmax -> subtract -> swish -> channel max ----
        float best0 = -CUDART_INF_F, best1 = -CUDART_INF_F;
        #pragma unroll 4
        for (int c = 0; c < COUT; ++c) {
            const float sub = wsm[c * WSTRIDE + 82];   // broadcast
            const float e0 = esm[wid][c][0][lane];
            const float e1 = esm[wid][c][1][lane];
            const float z0 = fmaf(e0, rS0, -sub);
            const float z1 = fmaf(e1, rS1, -sub);
            best0 = fmaxf(best0, __fdividef(z0, 1.f + __expf(-z0)));
            best1 = fmaxf(best1, __fdividef(z1, 1.f + __expf(-z1)));
        }

        float* orow = out + row * DIM;
        orow[2 * lane]     = best0;
        orow[2 * lane + 1] = best1;
        __syncwarp();   // tile reuse barrier before next row
    }
}

extern "C" void kernel_launch(void* const* d_in, const int* in_sizes, int n_in,
                              void* d_out, int out_size) {
    const float* x   = (const float*)d_in[0];
    const float* w   = (const float*)d_in[1];
    const float* b   = (const float*)d_in[2];
    const float* sub = (const float*)d_in[3];
    float* out = (float*)d_out;
    (void)in_sizes; (void)n_in; (void)out_size;

    // exact-fit persistent grid: occupancy-determined blocks/SM x numSMs
    int dev = 0, sms = 148, bpm = 4;
    cudaGetDevice(&dev);
    cudaDeviceGetAttribute(&sms, cudaDevAttrMultiProcessorCount, dev);
    cudaOccupancyMaxActiveBlocksPerMultiprocessor(&bpm, fused_ctmp_softswish_kernel, 128, 0);
    if (bpm < 1) bpm = 1;
    fused_ctmp_softswish_kernel<<<sms * bpm, 128>>>(x, w, b, sub, out);
}